// round 10
// baseline (speedup 1.0000x reference)
#include <cuda_runtime.h>
#include <cstdint>

#define CIN   32
#define NK    64
#define HW    128
#define NTH   512

#define WPAD 144   // u32 words per (t,p) row: 128 data + 16 pad  (mod 32 == 16)
#define APAD 272   // u32 words per (row,p) row: 260 data + 12 pad (mod 32 == 16)

// smem layout (bytes)
#define WS_OFF   0                          // 9*16*WPAD*4 = 82944
#define AB_OFF   82944                      // 6*16*APAD*4 = 104448
#define BIAS_OFF (82944 + 104448)
#define SMEM_TOTAL (BIAS_OFF + 256)         // 187648

__device__ __forceinline__ uint32_t f2tf32(float f) {
    uint32_t r;
    asm("cvt.rna.tf32.f32 %0, %1;" : "=r"(r) : "f"(f));
    return r;
}

__device__ __forceinline__ void mma_tf32(float* c,
                                         uint32_t a0, uint32_t a1, uint32_t a2, uint32_t a3,
                                         uint32_t b0, uint32_t b1) {
    asm volatile(
        "mma.sync.aligned.m16n8k8.row.col.f32.tf32.tf32.f32 "
        "{%0,%1,%2,%3}, {%4,%5,%6,%7}, {%8,%9}, {%0,%1,%2,%3};"
        : "+f"(c[0]), "+f"(c[1]), "+f"(c[2]), "+f"(c[3])
        : "r"(a0), "r"(a1), "r"(a2), "r"(a3), "r"(b0), "r"(b1));
}

__global__ void __launch_bounds__(NTH, 1)
conv_mma_kernel(const float* __restrict__ x, const float* __restrict__ kern,
                const float* __restrict__ bias, float* __restrict__ out)
{
    extern __shared__ __align__(16) char smem[];
    uint32_t* ws = (uint32_t*)(smem + WS_OFF);
    uint32_t* ab = (uint32_t*)(smem + AB_OFF);
    float*    bs = (float*)(smem + BIAS_OFF);

    const int tid  = threadIdx.x;
    const int lane = tid & 31;
    const int wid  = tid >> 5;       // 0..15
    const int g    = lane >> 2;      // 0..7
    const int q    = lane & 3;       // 0..3

    const int h0 = blockIdx.x * 4;   // 4 output rows per CTA
    const int n  = blockIdx.y;       // image

    // ---- stage weights ----
    // c decomposes: kg=c>>3, q=c&3, h=(c>>2)&1, p = kg*4 + q
    // ws[(t*16+p)*WPAD + k*2 + h] = tf32(kern[k][c*9+t])
    for (int i = tid; i < NK * CIN * 9; i += NTH) {
        const int k   = i / 288;
        const int rem = i - k * 288;
        const int c   = rem / 9;
        const int t   = rem - c * 9;
        const int p   = ((c >> 3) << 2) | (c & 3);
        const int h   = (c >> 2) & 1;
        ws[(t * 16 + p) * WPAD + k * 2 + h] = f2tf32(kern[i]);
    }

    // ---- stage inputs: 6 rows (h0-1 .. h0+4), halo of 1 in w ----
    // ab[(row*16+p)*APAD + j*2 + h] = tf32(x[n][c][h0-1+row][j-1])
    for (int i = tid; i < 6 * CIN * 130; i += NTH) {
        const int row = i / (CIN * 130);
        const int rem = i - row * (CIN * 130);
        const int c   = rem / 130;
        const int j   = rem - c * 130;
        const int gh  = h0 - 1 + row;
        const int gw  = j - 1;
        float v = 0.0f;
        if ((unsigned)gh < (unsigned)HW && (unsigned)gw < (unsigned)HW)
            v = x[(((size_t)n * CIN + c) * HW + gh) * HW + gw];
        const int p = ((c >> 3) << 2) | (c & 3);
        const int h = (c >> 2) & 1;
        ab[(row * 16 + p) * APAD + j * 2 + h] = f2tf32(v);
    }

    if (tid < NK) bs[tid] = bias[tid];
    __syncthreads();

    // ---- main GEMM: M=512 (4 rows x 128 w), N=64, K=288 ----
    const int wrow = wid >> 2;        // CTA output row 0..3
    const int wb   = (wid & 3) * 32;  // w base

    float acc[2][8][4];
    #pragma unroll
    for (int mt = 0; mt < 2; ++mt)
        #pragma unroll
        for (int nt = 0; nt < 8; ++nt)
            #pragma unroll
            for (int j = 0; j < 4; ++j) acc[mt][nt][j] = 0.0f;

    for (int r = 0; r < 3; ++r) {
        for (int s = 0; s < 3; ++s) {
            const int t = r * 3 + s;
            #pragma unroll
            for (int kg = 0; kg < 4; ++kg) {
                const int p = kg * 4 + q;
                const uint32_t* wt = ws + (t * 16 + p) * WPAD + g * 2;
                const uint32_t* ar = ab + ((wrow + r) * 16 + p) * APAD + (wb + g + s) * 2;

                uint2 B[8];
                #pragma unroll
                for (int nt = 0; nt < 8; ++nt)
                    B[nt] = *(const uint2*)(wt + nt * 16);   // (b0: c=cq, b1: c=cq+4)

                #pragma unroll
                for (int mt = 0; mt < 2; ++mt) {
                    const uint2 pa = *(const uint2*)(ar + mt * 32);        // (a0, a2)
                    const uint2 pb = *(const uint2*)(ar + mt * 32 + 16);   // (a1, a3)
                    #pragma unroll
                    for (int nt = 0; nt < 8; ++nt)
                        mma_tf32(acc[mt][nt], pa.x, pb.x, pa.y, pb.y,
                                 B[nt].x, B[nt].y);
                }
            }
        }
    }

    // ---- epilogue via smem bounce: coalesced w-major stores ----
    float* cb = (float*)(smem + AB_OFF);   // [512][33] = 67584 B (fits in abuf)
    #pragma unroll 1
    for (int half = 0; half < 2; ++half) {
        __syncthreads();   // abuf reads done (half 0) / out stores done (half 1)
        #pragma unroll
        for (int mt = 0; mt < 2; ++mt) {
            const int m0 = wid * 32 + mt * 16 + g;
            #pragma unroll
            for (int nto = 0; nto < 4; ++nto) {
                const int nt = half * 4 + nto;
                const int kk = nto * 8 + 2 * q;
                cb[m0 * 33 + kk]           = acc[mt][nt][0];
                cb[m0 * 33 + kk + 1]       = acc[mt][nt][1];
                cb[(m0 + 8) * 33 + kk]     = acc[mt][nt][2];
                cb[(m0 + 8) * 33 + kk + 1] = acc[mt][nt][3];
            }
        }
        __syncthreads();
        // 512 m x 32 k floats -> out[n][half*32+kk][h0 + m/128][m%128]
        #pragma unroll
        for (int it = 0; it < 32; ++it) {
            const int idx = it * NTH + tid;
            const int m   = idx & 511;
            const int kk  = idx >> 9;
            const int k   = half * 32 + kk;
            out[(((size_t)n * NK + k) * HW + (h0 + (m >> 7))) * HW + (m & 127)] =
                cb[m * 33 + kk] + bs[k];
        }
    }
}

extern "C" void kernel_launch(void* const* d_in, const int* in_sizes, int n_in,
                              void* d_out, int out_size)
{
    const float* x    = (const float*)d_in[0];
    const float* kern = (const float*)d_in[1];
    const float* bias = (const float*)d_in[2];
    float* out = (float*)d_out;

    cudaFuncSetAttribute(conv_mma_kernel,
                         cudaFuncAttributeMaxDynamicSharedMemorySize, SMEM_TOTAL);

    dim3 grid(HW / 4, 32, 1);   // (32, 32)
    dim3 block(NTH, 1, 1);
    conv_mma_kernel<<<grid, block, SMEM_TOTAL>>>(x, kern, bias, out);
}

// round 12
// speedup vs baseline: 1.8455x; 1.8455x over previous
#include <cuda_runtime.h>
#include <cstdint>

#define CIN   32
#define NK    64
#define HW    128
#define NTH   512
#define TILES 4          // 4-row tiles per CTA (16 rows total)

// smem layout (bytes)
#define WS_OFF   0                         // 9*32*72*4 = 82944
#define AB_OFF   82944                     // 6*32*136*4 = 104448
#define BIAS_OFF (82944 + 104448)          // 64 floats
#define SMEM_TOTAL (BIAS_OFF + 256)        // 187648

#define WSTRIDE 72     // weight k-stride (== 8 mod 32 -> conflict-free)
#define ASTRIDE 136    // input  w-stride (== 8 mod 32 -> conflict-free)

__device__ __forceinline__ uint32_t f2tf32(float f) {
    uint32_t r;
    asm("cvt.rna.tf32.f32 %0, %1;" : "=r"(r) : "f"(f));
    return r;
}

__device__ __forceinline__ void mma_tf32(float* c,
                                         uint32_t a0, uint32_t a1, uint32_t a2, uint32_t a3,
                                         uint32_t b0, uint32_t b1) {
    asm volatile(
        "mma.sync.aligned.m16n8k8.row.col.f32.tf32.tf32.f32 "
        "{%0,%1,%2,%3}, {%4,%5,%6,%7}, {%8,%9}, {%0,%1,%2,%3};"
        : "+f"(c[0]), "+f"(c[1]), "+f"(c[2]), "+f"(c[3])
        : "r"(a0), "r"(a1), "r"(a2), "r"(a3), "r"(b0), "r"(b1));
}

// stage input absrows [r0, r0+cnt) into ring slot (absrow+1)%6
__device__ __forceinline__ void stage_rows(uint32_t* ab, const float* __restrict__ x,
                                           int n, int r0, int cnt, int tid) {
    for (int i = tid; i < cnt * CIN * 130; i += NTH) {
        const int row = i / (CIN * 130);
        const int rem = i - row * (CIN * 130);
        const int c   = rem / 130;
        const int j   = rem - c * 130;
        const int gh  = r0 + row;
        const int gw  = j - 1;
        float v = 0.0f;
        if ((unsigned)gh < (unsigned)HW && (unsigned)gw < (unsigned)HW)
            v = x[(((size_t)n * CIN + c) * HW + gh) * HW + gw];
        const int slot = (gh + 1) % 6;
        ab[(slot * CIN + c) * ASTRIDE + j] = f2tf32(v);
    }
}

__global__ void __launch_bounds__(NTH, 1)
conv_mma_kernel(const float* __restrict__ x, const float* __restrict__ kern,
                const float* __restrict__ bias, float* __restrict__ out)
{
    extern __shared__ __align__(16) char smem[];
    uint32_t* ws = (uint32_t*)(smem + WS_OFF);
    uint32_t* ab = (uint32_t*)(smem + AB_OFF);
    float*    bs = (float*)(smem + BIAS_OFF);

    const int tid  = threadIdx.x;
    const int lane = tid & 31;
    const int wid  = tid >> 5;       // 0..15
    const int g    = lane >> 2;      // 0..7
    const int q    = lane & 3;       // 0..3

    const int hbase = blockIdx.x * (4 * TILES);   // 16 rows per CTA
    const int n     = blockIdx.y;                 // image

    // ---- stage weights once: ws[t][c][k] = tf32(kern[k][c*9+t]) ----
    for (int i = tid; i < NK * CIN * 9; i += NTH) {
        const int k   = i / 288;
        const int rem = i - k * 288;
        const int c   = rem / 9;
        const int t   = rem - c * 9;
        ws[(t * CIN + c) * WSTRIDE + k] = f2tf32(kern[i]);
    }
    if (tid < NK) bs[tid] = bias[tid];

    // ---- initial A stage: absrows hbase-1 .. hbase+4 ----
    stage_rows(ab, x, n, hbase - 1, 6, tid);
    __syncthreads();

    const int wrow = wid >> 2;        // CTA output row 0..3
    const int wb   = (wid & 3) * 32;  // w base
    const int w0l  = wb + g;          // lane's base w

    for (int t = 0; t < TILES; ++t) {
        const int h0 = hbase + 4 * t;

        float acc[2][8][4];
        #pragma unroll
        for (int mt = 0; mt < 2; ++mt)
            #pragma unroll
            for (int nt = 0; nt < 8; ++nt)
                #pragma unroll
                for (int j = 0; j < 4; ++j) acc[mt][nt][j] = 0.0f;

        // ---- mainloop: M=512, N=64, K=288 ----
        for (int r = 0; r < 3; ++r) {
            const int slot = (h0 + wrow + r) % 6;
            const uint32_t* arow = ab + slot * CIN * ASTRIDE;
            for (int s = 0; s < 3; ++s) {
                const uint32_t* wt = ws + (r * 3 + s) * CIN * WSTRIDE;
                #pragma unroll
                for (int kg = 0; kg < 4; ++kg) {
                    const int cq = kg * 8 + q;

                    uint32_t B[8][2];
                    #pragma unroll
                    for (int nt = 0; nt < 8; ++nt) {
                        B[nt][0] = wt[cq * WSTRIDE + nt * 8 + g];
                        B[nt][1] = wt[(cq + 4) * WSTRIDE + nt * 8 + g];
                    }

                    #pragma unroll
                    for (int mt = 0; mt < 2; ++mt) {
                        const int w0 = w0l + mt * 16 + s;
                        const uint32_t a0 = arow[cq * ASTRIDE + w0];
                        const uint32_t a1 = arow[cq * ASTRIDE + w0 + 8];
                        const uint32_t a2 = arow[(cq + 4) * ASTRIDE + w0];
                        const uint32_t a3 = arow[(cq + 4) * ASTRIDE + w0 + 8];
                        #pragma unroll
                        for (int nt = 0; nt < 8; ++nt)
                            mma_tf32(acc[mt][nt], a0, a1, a2, a3, B[nt][0], B[nt][1]);
                    }
                }
            }
        }

        // ---- direct epilogue: per STG instr a warp hits 4 k-planes x 32B = 4 full sectors ----
        {
            float* ob = out + ((size_t)n * NK) * HW * HW + (size_t)(h0 + wrow) * HW;
            #pragma unroll
            for (int mt = 0; mt < 2; ++mt) {
                const int w = w0l + mt * 16;
                #pragma unroll
                for (int nt = 0; nt < 8; ++nt) {
                    const int kn = nt * 8 + 2 * q;
                    const float b0 = bs[kn];
                    const float b1 = bs[kn + 1];
                    float* p0 = ob + (size_t)kn * HW * HW + w;
                    float* p1 = ob + (size_t)(kn + 1) * HW * HW + w;
                    p0[0] = acc[mt][nt][0] + b0;
                    p1[0] = acc[mt][nt][1] + b1;
                    p0[8] = acc[mt][nt][2] + b0;
                    p1[8] = acc[mt][nt][3] + b1;
                }
            }
        }

        // ---- stage 4 new rows for next tile (absrows h0+5 .. h0+8) ----
        if (t < TILES - 1) {
            __syncthreads();               // all warps done reading ab
            stage_rows(ab, x, n, h0 + 5, 4, tid);
            __syncthreads();
        }
    }
}

extern "C" void kernel_launch(void* const* d_in, const int* in_sizes, int n_in,
                              void* d_out, int out_size)
{
    const float* x    = (const float*)d_in[0];
    const float* kern = (const float*)d_in[1];
    const float* bias = (const float*)d_in[2];
    float* out = (float*)d_out;

    cudaFuncSetAttribute(conv_mma_kernel,
                         cudaFuncAttributeMaxDynamicSharedMemorySize, SMEM_TOTAL);

    dim3 grid(HW / (4 * TILES), 32, 1);   // (8, 32)
    dim3 block(NTH, 1, 1);
    conv_mma_kernel<<<grid, block, SMEM_TOTAL>>>(x, kern, bias, out);
}